// round 5
// baseline (speedup 1.0000x reference)
#include <cuda_runtime.h>

// Problem constants (fixed by the dataset)
#define NN   100000
#define EE   1600000
#define DINK 128
#define HH   64
#define GGR  512

// Scratch (no allocations allowed -> __device__ globals)
__device__ float g_p   [NN * HH];   // projected features  p = h @ W1
__device__ float g_aggr[NN * HH];   // neighbor sums of p
__device__ float g_h   [NN * HH];   // layer output
__device__ float g_pool[GGR * HH];  // graph pooling

// ---------------------------------------------------------------------------
// vector f32 reduction to global (sm_90+): 16B per instruction, no return
// ---------------------------------------------------------------------------
__device__ __forceinline__ void red4(float* a, float4 v) {
    asm volatile("red.global.add.v4.f32 [%0], {%1,%2,%3,%4};"
                 :: "l"(a), "f"(v.x), "f"(v.y), "f"(v.z), "f"(v.w)
                 : "memory");
}

__global__ void zero_kernel(float4* p, int n4) {
    int i = blockIdx.x * blockDim.x + threadIdx.x;
    if (i < n4) p[i] = make_float4(0.f, 0.f, 0.f, 0.f);
}

// ---------------------------------------------------------------------------
// C[nrows x 64] = op(A) @ W[K x 64]
//   PRE:       op(A) = relu(A + A2 + bpre)   (elementwise, 64-dim rows)
//   POST_BIAS: += bpost
//   POST_RELU: relu
//   ZERO_AUX:  also write zeros to AUX at the same [row, col] positions
//              (fuses the aggr-buffer clear into the projection GEMM)
// Block: 256 threads, 64 rows/block, K processed in 64-wide chunks.
// Each thread computes a 4x4 register tile (16 FMA per k-step, ~2B LDS/FMA).
// ---------------------------------------------------------------------------
template <int K, bool PRE, bool POST_BIAS, bool POST_RELU, bool ZERO_AUX>
__global__ void gemm64(const float* __restrict__ A,
                       const float* __restrict__ A2,
                       const float* __restrict__ bpre,
                       const float* __restrict__ W,
                       const float* __restrict__ bpost,
                       float* __restrict__ C,
                       float* __restrict__ AUX,
                       int nrows) {
    constexpr int RB   = 64;        // rows per block
    constexpr int KC   = 64;        // k-chunk
    constexpr int ASTR = KC + 4;    // pad: avoid bank conflicts across rows

    __shared__ float Ws[KC * 64];
    __shared__ float As[RB * ASTR];

    const int tid  = threadIdx.x;
    const int row0 = blockIdx.x * RB;
    const int tc   = tid & 15;      // 16 column groups of 4
    const int tr   = tid >> 4;      // 16 row groups of 4

    float4 acc[4];
#pragma unroll
    for (int r = 0; r < 4; r++) acc[r] = make_float4(0.f, 0.f, 0.f, 0.f);

    for (int kb = 0; kb < K; kb += KC) {
        // --- stage W chunk (contiguous KC*64 floats) ---
        for (int i = tid; i < KC * 64 / 4; i += 256)
            ((float4*)Ws)[i] = ((const float4*)(W + (size_t)kb * 64))[i];

        // --- stage A chunk with optional pre-op ---
        for (int i = tid; i < RB * KC / 4; i += 256) {
            int r   = i / (KC / 4);
            int kk  = (i % (KC / 4)) * 4;
            int row = row0 + r;
            float4 v = make_float4(0.f, 0.f, 0.f, 0.f);
            if (row < nrows) {
                v = *(const float4*)(A + (size_t)row * K + kb + kk);
                if constexpr (PRE) {
                    float4 u = *(const float4*)(A2 + (size_t)row * K + kb + kk);
                    float4 b = *(const float4*)(bpre + kb + kk);
                    v.x = fmaxf(v.x + u.x + b.x, 0.f);
                    v.y = fmaxf(v.y + u.y + b.y, 0.f);
                    v.z = fmaxf(v.z + u.z + b.z, 0.f);
                    v.w = fmaxf(v.w + u.w + b.w, 0.f);
                }
            }
            *(float4*)(As + r * ASTR + kk) = v;
        }
        __syncthreads();

#pragma unroll 16
        for (int k = 0; k < KC; k++) {
            float4 w = *(const float4*)(Ws + k * 64 + tc * 4);
#pragma unroll
            for (int r = 0; r < 4; r++) {
                float a = As[(tr * 4 + r) * ASTR + k];
                acc[r].x += a * w.x;
                acc[r].y += a * w.y;
                acc[r].z += a * w.z;
                acc[r].w += a * w.w;
            }
        }
        __syncthreads();
    }

    float4 bp = make_float4(0.f, 0.f, 0.f, 0.f);
    if constexpr (POST_BIAS) bp = *(const float4*)(bpost + tc * 4);

#pragma unroll
    for (int r = 0; r < 4; r++) {
        int row = row0 + tr * 4 + r;
        if (row < nrows) {
            float4 o = acc[r];
            if constexpr (POST_BIAS) {
                o.x += bp.x; o.y += bp.y; o.z += bp.z; o.w += bp.w;
            }
            if constexpr (POST_RELU) {
                o.x = fmaxf(o.x, 0.f); o.y = fmaxf(o.y, 0.f);
                o.z = fmaxf(o.z, 0.f); o.w = fmaxf(o.w, 0.f);
            }
            *(float4*)(C + (size_t)row * 64 + tc * 4) = o;
            if constexpr (ZERO_AUX) {
                *(float4*)(AUX + (size_t)row * 64 + tc * 4) =
                    make_float4(0.f, 0.f, 0.f, 0.f);
            }
        }
    }
}

// ---------------------------------------------------------------------------
// Scatter-add aggregation over edges: aggr[dst] += p[src], 64 floats per edge.
// 16 threads per edge, float4 lanes. p/aggr are L2-resident (25.6 MB each).
// ---------------------------------------------------------------------------
__global__ void edge_aggr(const float* __restrict__ p,
                          const int* __restrict__ src,
                          const int* __restrict__ dst,
                          float* __restrict__ aggr) {
    int t = blockIdx.x * blockDim.x + threadIdx.x;
    int e = t >> 4;
    if (e >= EE) return;
    int part = (t & 15) * 4;
    int s = __ldg(src + e);
    int d = __ldg(dst + e);
    float4 v = *(const float4*)(p + (size_t)s * 64 + part);
    red4(aggr + (size_t)d * 64 + part, v);
}

// global_add_pool: pool[batch[n]] += h[n]
__global__ void pool_kernel(const float* __restrict__ h,
                            const int* __restrict__ batch,
                            float* __restrict__ pool) {
    int t = blockIdx.x * blockDim.x + threadIdx.x;
    int node = t >> 4;
    if (node >= NN) return;
    int part = (t & 15) * 4;
    int b = __ldg(batch + node);
    float4 v = *(const float4*)(h + (size_t)node * 64 + part);
    red4(pool + (size_t)b * 64 + part, v);
}

// out[512 x 16] = t[512 x 64] @ mw2[64 x 16] + mb2
__global__ void readout2(const float* __restrict__ t,
                         const float* __restrict__ mw2,
                         const float* __restrict__ mb2,
                         float* __restrict__ out) {
    __shared__ float Ws[64 * 16];
    int tid = threadIdx.x;
    for (int i = tid; i < 64 * 16 / 4; i += blockDim.x)
        ((float4*)Ws)[i] = ((const float4*)mw2)[i];
    __syncthreads();

    int idx = blockIdx.x * blockDim.x + tid;
    if (idx >= GGR * 16) return;
    int g = idx >> 4, c = idx & 15;
    float s = __ldg(mb2 + c);
    const float* tr_ = t + (size_t)g * 64;
#pragma unroll
    for (int k = 0; k < 64; k++) s += tr_[k] * Ws[k * 16 + c];
    out[idx] = s;
}

// ---------------------------------------------------------------------------
// Launch: GIN layer trick — (h + sum_N h) @ W1 == p + sum_N p with p = h @ W1,
// so every edge pass runs at 64-dim regardless of input dim. The projection
// GEMM also zeros the aggr buffer for its rows (ZERO_AUX), removing the
// standalone clear pass.
// ---------------------------------------------------------------------------
extern "C" void kernel_launch(void* const* d_in, const int* in_sizes, int n_in,
                              void* d_out, int out_size) {
    const float* x     = (const float*)d_in[0];
    const int*   ei    = (const int*)d_in[1];
    const int*   batch = (const int*)d_in[2];
    const float* w1_0  = (const float*)d_in[3];
    const float* b1_0  = (const float*)d_in[4];
    const float* w2_0  = (const float*)d_in[5];
    const float* b2_0  = (const float*)d_in[6];
    const float* w1_r  = (const float*)d_in[7];
    const float* b1_r  = (const float*)d_in[8];
    const float* w2_r  = (const float*)d_in[9];
    const float* b2_r  = (const float*)d_in[10];
    const float* mw1   = (const float*)d_in[11];
    const float* mb1   = (const float*)d_in[12];
    const float* mw2   = (const float*)d_in[13];
    const float* mb2   = (const float*)d_in[14];

    const int* src = ei;
    const int* dst = ei + EE;

    float *p, *aggr, *h, *pool;
    cudaGetSymbolAddress((void**)&p,    g_p);
    cudaGetSymbolAddress((void**)&aggr, g_aggr);
    cudaGetSymbolAddress((void**)&h,    g_h);
    cudaGetSymbolAddress((void**)&pool, g_pool);

    const int gemm_blocks = (NN + 63) / 64;             // 1563
    const int edge_blocks = (EE * 16 + 255) / 256;      // 100000
    const int node_blocks = (NN * 16 + 255) / 256;      // 6250

    // Layer 0 (DIN=128 -> 64): project + zero aggr in one pass
    gemm64<DINK, false, false, false, true><<<gemm_blocks, 256>>>(
        x, nullptr, nullptr, w1_0, nullptr, p, aggr, NN);
    edge_aggr<<<edge_blocks, 256>>>(p, src, dst, aggr);
    gemm64<HH, true, true, true, false><<<gemm_blocks, 256>>>(
        p, aggr, b1_0, w2_0, b2_0, h, nullptr, NN);

    // Layers 1..4 (64 -> 64)
    for (int i = 0; i < 4; i++) {
        gemm64<HH, false, false, false, true><<<gemm_blocks, 256>>>(
            h, nullptr, nullptr, w1_r + (size_t)i * HH * HH, nullptr, p, aggr, NN);
        edge_aggr<<<edge_blocks, 256>>>(p, src, dst, aggr);
        gemm64<HH, true, true, true, false><<<gemm_blocks, 256>>>(
            p, aggr, b1_r + (size_t)i * HH, w2_r + (size_t)i * HH * HH,
            b2_r + (size_t)i * HH, h, nullptr, NN);
    }

    // Pool + readout
    zero_kernel<<<(GGR * HH / 4 + 255) / 256, 256>>>((float4*)pool, GGR * HH / 4);
    pool_kernel<<<node_blocks, 256>>>(h, batch, pool);
    gemm64<HH, false, true, true, false><<<(GGR + 63) / 64, 256>>>(
        pool, nullptr, nullptr, mw1, mb1, p /* reuse as t */, nullptr, GGR);
    readout2<<<(GGR * 16 + 255) / 256, 256>>>(p, mw2, mb2, (float*)d_out);
}

// round 6
// speedup vs baseline: 1.6317x; 1.6317x over previous
#include <cuda_runtime.h>

// Problem constants (fixed by the dataset)
#define NN   100000
#define EE   1600000
#define DINK 128
#define HH   64
#define GGR  512

#define SCAN_B  512
#define SCAN_NB ((NN + SCAN_B - 1) / SCAN_B)   // 196

// Scratch (no allocations allowed -> __device__ globals)
__device__ float g_p   [NN * HH];     // ping buffer (projected feats)
__device__ float g_h   [NN * HH];     // pong buffer
__device__ float g_pool[GGR * HH];    // graph pooling
__device__ int   g_deg [NN];          // degree, then CSR cursor
__device__ int   g_rowptr[NN + 1];
__device__ int   g_csr [EE];          // src list grouped by dst
__device__ int   g_bsums[SCAN_NB];

// ---------------------------------------------------------------------------
__device__ __forceinline__ void red4(float* a, float4 v) {
    asm volatile("red.global.add.v4.f32 [%0], {%1,%2,%3,%4};"
                 :: "l"(a), "f"(v.x), "f"(v.y), "f"(v.z), "f"(v.w)
                 : "memory");
}
__device__ __forceinline__ float4 f4zero() { return make_float4(0.f,0.f,0.f,0.f); }

// ---------------------------------------------------------------------------
// CSR build: zero -> hist -> scan(3 kernels) -> scatter
// ---------------------------------------------------------------------------
__global__ void zero_init() {           // deg = 0, pool = 0
    int i = blockIdx.x * blockDim.x + threadIdx.x;
    if (i < NN) g_deg[i] = 0;
    if (i < GGR * HH) g_pool[i] = 0.f;
}

__global__ void hist_kernel(const int* __restrict__ dst) {
    int e = blockIdx.x * blockDim.x + threadIdx.x;
    if (e < EE) atomicAdd(&g_deg[dst[e]], 1);
}

__global__ void scan1_kernel() {        // block-local exclusive scan of deg
    __shared__ int s[2][SCAN_B];
    int t = threadIdx.x;
    int i = blockIdx.x * SCAN_B + t;
    int v = (i < NN) ? g_deg[i] : 0;
    int pin = 0;
    s[0][t] = v;
    __syncthreads();
#pragma unroll
    for (int off = 1; off < SCAN_B; off <<= 1) {
        int x = s[pin][t];
        if (t >= off) x += s[pin][t - off];
        pin ^= 1;
        s[pin][t] = x;
        __syncthreads();
    }
    int incl = s[pin][t];
    if (i < NN) g_rowptr[i] = incl - v;            // exclusive prefix
    if (t == SCAN_B - 1) g_bsums[blockIdx.x] = incl;
}

__global__ void scan2_kernel() {        // exclusive scan of 196 block sums
    __shared__ int s[256];
    int t = threadIdx.x;
    s[t] = (t < SCAN_NB) ? g_bsums[t] : 0;
    __syncthreads();
    if (t == 0) {
        int acc = 0;
        for (int b = 0; b < SCAN_NB; b++) { int x = s[b]; s[b] = acc; acc += x; }
    }
    __syncthreads();
    if (t < SCAN_NB) g_bsums[t] = s[t];
}

__global__ void scan3_kernel() {        // finalize rowptr, init cursor (=deg)
    int i = blockIdx.x * blockDim.x + threadIdx.x;
    if (i < NN) {
        int v = g_rowptr[i] + g_bsums[i / SCAN_B];
        g_rowptr[i] = v;
        g_deg[i]    = v;                // cursor for scatter
    }
    if (i == 0) g_rowptr[NN] = EE;
}

__global__ void scatter_kernel(const int* __restrict__ src,
                               const int* __restrict__ dst) {
    int e = blockIdx.x * blockDim.x + threadIdx.x;
    if (e < EE) {
        int pos = atomicAdd(&g_deg[dst[e]], 1);
        g_csr[pos] = src[e];
    }
}

// ---------------------------------------------------------------------------
// Plain GEMM  C[nrows x 64] = A[nrows x K] @ W[K x 64]  (+bias, +relu opts)
// Used for the input projection (K=128) and readout MLP layer 1.
// ---------------------------------------------------------------------------
template <int K, bool POST_BIAS, bool POST_RELU>
__global__ __launch_bounds__(256) void gemm64(
        const float* __restrict__ A, const float* __restrict__ W,
        const float* __restrict__ bpost, float* __restrict__ C, int nrows) {
    constexpr int ASTR = 68;
    __shared__ float Ws[64 * 64];
    __shared__ float As[64 * ASTR];

    const int tid  = threadIdx.x;
    const int row0 = blockIdx.x * 64;
    const int tc   = tid & 15;
    const int tr   = tid >> 4;

    float4 acc[4];
#pragma unroll
    for (int r = 0; r < 4; r++) acc[r] = f4zero();

    for (int kb = 0; kb < K; kb += 64) {
        for (int i = tid; i < 64 * 64 / 4; i += 256)
            ((float4*)Ws)[i] = ((const float4*)(W + (size_t)kb * 64))[i];
        for (int i = tid; i < 64 * 64 / 4; i += 256) {
            int r  = i / 16;
            int kk = (i % 16) * 4;
            int row = row0 + r;
            float4 v = f4zero();
            if (row < nrows) v = *(const float4*)(A + (size_t)row * K + kb + kk);
            *(float4*)(As + r * ASTR + kk) = v;
        }
        __syncthreads();
#pragma unroll 16
        for (int k = 0; k < 64; k++) {
            float4 w = *(const float4*)(Ws + k * 64 + tc * 4);
#pragma unroll
            for (int r = 0; r < 4; r++) {
                float a = As[(tr * 4 + r) * ASTR + k];
                acc[r].x += a * w.x; acc[r].y += a * w.y;
                acc[r].z += a * w.z; acc[r].w += a * w.w;
            }
        }
        __syncthreads();
    }

    float4 bp = f4zero();
    if constexpr (POST_BIAS) bp = *(const float4*)(bpost + tc * 4);
#pragma unroll
    for (int r = 0; r < 4; r++) {
        int row = row0 + tr * 4 + r;
        if (row < nrows) {
            float4 o = acc[r];
            if constexpr (POST_BIAS) {
                o.x += bp.x; o.y += bp.y; o.z += bp.z; o.w += bp.w;
            }
            if constexpr (POST_RELU) {
                o.x = fmaxf(o.x, 0.f); o.y = fmaxf(o.y, 0.f);
                o.z = fmaxf(o.z, 0.f); o.w = fmaxf(o.w, 0.f);
            }
            *(float4*)(C + (size_t)row * 64 + tc * 4) = o;
        }
    }
}

// ---------------------------------------------------------------------------
// Fused GIN layer (64-dim):
//   per 64-row block:
//     phase1: As[r] = relu( p[r] + sum_{s in N(r)} p[s] + b1 )   (CSR gather)
//     phase2: H     = relu( As @ W2 + b2 )                        (regs -> As)
//     phase3: p_out = H @ W1n       (next layer's projection)
//   LAST layer: phase3 replaced by pool[batch[r]] += H[r]  (run-combined red)
// ---------------------------------------------------------------------------
template <bool LAST>
__global__ __launch_bounds__(256) void gin_fused(
        const float* __restrict__ p,
        const float* __restrict__ b1,
        const float* __restrict__ W2,
        const float* __restrict__ b2,
        const float* __restrict__ W1n,
        float* __restrict__ p_out,
        const int* __restrict__ batch,
        float* __restrict__ pool) {
    constexpr int ASTR = 68;
    __shared__ float Ws[64 * 64];
    __shared__ float As[64 * ASTR];

    const int tid  = threadIdx.x;
    const int row0 = blockIdx.x * 64;

    // stage W2 early (no dependency; gather sync covers it)
    for (int i = tid; i < 64 * 64 / 4; i += 256)
        ((float4*)Ws)[i] = ((const float4*)W2)[i];

    // ---- phase 1: CSR gather + self + b1 + relu into As ----
    {
        const int grp  = tid >> 4;        // 16 groups of 16 threads
        const int part = (tid & 15) * 4;  // float4 lane within the 64-dim row
        float4 b1v = *(const float4*)(b1 + part);
#pragma unroll
        for (int rr = 0; rr < 4; rr++) {
            int r   = grp * 4 + rr;
            int row = row0 + r;
            float4 acc = f4zero();
            if (row < NN) {
                int beg = __ldg(g_rowptr + row);
                int end = __ldg(g_rowptr + row + 1);
                int j = beg;
                for (; j + 4 <= end; j += 4) {     // 4-wide for MLP
                    int s0 = __ldg(g_csr + j);
                    int s1 = __ldg(g_csr + j + 1);
                    int s2 = __ldg(g_csr + j + 2);
                    int s3 = __ldg(g_csr + j + 3);
                    float4 v0 = *(const float4*)(p + (size_t)s0 * 64 + part);
                    float4 v1 = *(const float4*)(p + (size_t)s1 * 64 + part);
                    float4 v2 = *(const float4*)(p + (size_t)s2 * 64 + part);
                    float4 v3 = *(const float4*)(p + (size_t)s3 * 64 + part);
                    acc.x += (v0.x + v1.x) + (v2.x + v3.x);
                    acc.y += (v0.y + v1.y) + (v2.y + v3.y);
                    acc.z += (v0.z + v1.z) + (v2.z + v3.z);
                    acc.w += (v0.w + v1.w) + (v2.w + v3.w);
                }
                for (; j < end; j++) {
                    int s = __ldg(g_csr + j);
                    float4 v = *(const float4*)(p + (size_t)s * 64 + part);
                    acc.x += v.x; acc.y += v.y; acc.z += v.z; acc.w += v.w;
                }
                float4 self = *(const float4*)(p + (size_t)row * 64 + part);
                acc.x = fmaxf(acc.x + self.x + b1v.x, 0.f);
                acc.y = fmaxf(acc.y + self.y + b1v.y, 0.f);
                acc.z = fmaxf(acc.z + self.z + b1v.z, 0.f);
                acc.w = fmaxf(acc.w + self.w + b1v.w, 0.f);
            }
            *(float4*)(As + r * ASTR + part) = acc;
        }
    }
    __syncthreads();

    const int tc = tid & 15;
    const int tr = tid >> 4;

    // ---- phase 2: H = relu(As @ W2 + b2) ----
    float4 acc[4];
#pragma unroll
    for (int r = 0; r < 4; r++) acc[r] = f4zero();
#pragma unroll 16
    for (int k = 0; k < 64; k++) {
        float4 w = *(const float4*)(Ws + k * 64 + tc * 4);
#pragma unroll
        for (int r = 0; r < 4; r++) {
            float a = As[(tr * 4 + r) * ASTR + k];
            acc[r].x += a * w.x; acc[r].y += a * w.y;
            acc[r].z += a * w.z; acc[r].w += a * w.w;
        }
    }
    float4 b2v = *(const float4*)(b2 + tc * 4);
#pragma unroll
    for (int r = 0; r < 4; r++) {
        acc[r].x = fmaxf(acc[r].x + b2v.x, 0.f);
        acc[r].y = fmaxf(acc[r].y + b2v.y, 0.f);
        acc[r].z = fmaxf(acc[r].z + b2v.z, 0.f);
        acc[r].w = fmaxf(acc[r].w + b2v.w, 0.f);
    }

    if constexpr (LAST) {
        // ---- pool epilogue: pool[batch[row]] += H[row], run-combined ----
        int b_prev = -1;
        float4 run = f4zero();
#pragma unroll
        for (int r = 0; r < 4; r++) {
            int row = row0 + tr * 4 + r;
            if (row < NN) {
                int b = __ldg(batch + row);
                if (b == b_prev) {
                    run.x += acc[r].x; run.y += acc[r].y;
                    run.z += acc[r].z; run.w += acc[r].w;
                } else {
                    if (b_prev >= 0)
                        red4(pool + (size_t)b_prev * 64 + tc * 4, run);
                    b_prev = b; run = acc[r];
                }
            }
        }
        if (b_prev >= 0) red4(pool + (size_t)b_prev * 64 + tc * 4, run);
    } else {
        // ---- phase 3: p_out = H @ W1n ----
        __syncthreads();                      // all As/Ws reads of phase 2 done
#pragma unroll
        for (int r = 0; r < 4; r++)           // H -> As (reuse)
            *(float4*)(As + (tr * 4 + r) * ASTR + tc * 4) = acc[r];
        for (int i = tid; i < 64 * 64 / 4; i += 256)
            ((float4*)Ws)[i] = ((const float4*)W1n)[i];
        __syncthreads();

        float4 acc2[4];
#pragma unroll
        for (int r = 0; r < 4; r++) acc2[r] = f4zero();
#pragma unroll 16
        for (int k = 0; k < 64; k++) {
            float4 w = *(const float4*)(Ws + k * 64 + tc * 4);
#pragma unroll
            for (int r = 0; r < 4; r++) {
                float a = As[(tr * 4 + r) * ASTR + k];
                acc2[r].x += a * w.x; acc2[r].y += a * w.y;
                acc2[r].z += a * w.z; acc2[r].w += a * w.w;
            }
        }
#pragma unroll
        for (int r = 0; r < 4; r++) {
            int row = row0 + tr * 4 + r;
            if (row < NN)
                *(float4*)(p_out + (size_t)row * 64 + tc * 4) = acc2[r];
        }
    }
}

// out[512 x 16] = t[512 x 64] @ mw2[64 x 16] + mb2
__global__ void readout2(const float* __restrict__ t,
                         const float* __restrict__ mw2,
                         const float* __restrict__ mb2,
                         float* __restrict__ out) {
    __shared__ float Ws[64 * 16];
    int tid = threadIdx.x;
    for (int i = tid; i < 64 * 16 / 4; i += blockDim.x)
        ((float4*)Ws)[i] = ((const float4*)mw2)[i];
    __syncthreads();

    int idx = blockIdx.x * blockDim.x + tid;
    if (idx >= GGR * 16) return;
    int g = idx >> 4, c = idx & 15;
    float s = __ldg(mb2 + c);
    const float* tr_ = t + (size_t)g * 64;
#pragma unroll
    for (int k = 0; k < 64; k++) s += tr_[k] * Ws[k * 16 + c];
    out[idx] = s;
}

// ---------------------------------------------------------------------------
extern "C" void kernel_launch(void* const* d_in, const int* in_sizes, int n_in,
                              void* d_out, int out_size) {
    const float* x     = (const float*)d_in[0];
    const int*   ei    = (const int*)d_in[1];
    const int*   batch = (const int*)d_in[2];
    const float* w1_0  = (const float*)d_in[3];
    const float* b1_0  = (const float*)d_in[4];
    const float* w2_0  = (const float*)d_in[5];
    const float* b2_0  = (const float*)d_in[6];
    const float* w1_r  = (const float*)d_in[7];
    const float* b1_r  = (const float*)d_in[8];
    const float* w2_r  = (const float*)d_in[9];
    const float* b2_r  = (const float*)d_in[10];
    const float* mw1   = (const float*)d_in[11];
    const float* mb1   = (const float*)d_in[12];
    const float* mw2   = (const float*)d_in[13];
    const float* mb2   = (const float*)d_in[14];

    const int* src = ei;
    const int* dst = ei + EE;

    float *p, *h, *pool;
    cudaGetSymbolAddress((void**)&p,    g_p);
    cudaGetSymbolAddress((void**)&h,    g_h);
    cudaGetSymbolAddress((void**)&pool, g_pool);

    const int gemm_blocks = (NN + 63) / 64;        // 1563
    const int edge_blocks = (EE + 255) / 256;      // 6250
    const int node_blocks = (NN + 255) / 256;      // 391

    // --- CSR build (also zeroes pool) ---
    zero_init<<<node_blocks, 256>>>();
    hist_kernel<<<edge_blocks, 256>>>(dst);
    scan1_kernel<<<SCAN_NB, SCAN_B>>>();
    scan2_kernel<<<1, 256>>>();
    scan3_kernel<<<node_blocks, 256>>>();
    scatter_kernel<<<edge_blocks, 256>>>(src, dst);

    // --- input projection: p = x @ w1_0  (K=128) ---
    gemm64<DINK, false, false><<<gemm_blocks, 256>>>(x, w1_0, nullptr, p, NN);

    // --- 5 fused GIN layers, ping-ponging p <-> h ---
    gin_fused<false><<<gemm_blocks, 256>>>(p, b1_0, w2_0, b2_0,
                                           w1_r + 0 * HH * HH, h, nullptr, nullptr);
    gin_fused<false><<<gemm_blocks, 256>>>(h, b1_r + 0 * HH, w2_r + 0 * HH * HH,
                                           b2_r + 0 * HH, w1_r + 1 * HH * HH,
                                           p, nullptr, nullptr);
    gin_fused<false><<<gemm_blocks, 256>>>(p, b1_r + 1 * HH, w2_r + 1 * HH * HH,
                                           b2_r + 1 * HH, w1_r + 2 * HH * HH,
                                           h, nullptr, nullptr);
    gin_fused<false><<<gemm_blocks, 256>>>(h, b1_r + 2 * HH, w2_r + 2 * HH * HH,
                                           b2_r + 2 * HH, w1_r + 3 * HH * HH,
                                           p, nullptr, nullptr);
    gin_fused<true ><<<gemm_blocks, 256>>>(p, b1_r + 3 * HH, w2_r + 3 * HH * HH,
                                           b2_r + 3 * HH, nullptr,
                                           nullptr, batch, pool);

    // --- readout: relu(pool @ mw1 + mb1) @ mw2 + mb2 ---
    gemm64<HH, true, true><<<(GGR + 63) / 64, 256>>>(pool, mw1, mb1, h, GGR);
    readout2<<<(GGR * 16 + 255) / 256, 256>>>(h, mw2, mb2, (float*)d_out);
}